// round 1
// baseline (speedup 1.0000x reference)
#include <cuda_runtime.h>
#include <cuda_bf16.h>
#include <math.h>

#define NODES 50000
#define EDGES 800000
#define DF 64
#define HF 64
#define BN_EPS 1e-3f

// ---------------- device scratch (static, no allocs) ----------------
__device__ float g_Wm1[DF * HF];     // BN1-folded message W1
__device__ float g_cm1[HF];
__device__ float g_Wm2[HF * HF];     // BN2-folded message W2
__device__ float g_cm2[HF];
__device__ float g_Wu1[(DF + HF) * HF];  // BN-folded update W1 (128x64)
__device__ float g_cu1[HF];
__device__ float g_Wu2[HF * HF];     // BN-folded update W2
__device__ float g_cu2[HF];
__device__ float g_agg[(size_t)NODES * HF];  // segment sum accumulator
__device__ float g_cnt[NODES];               // segment counts

// ---------------- helpers ----------------
__device__ __forceinline__ float gelu_f(float v) {
    // exact gelu: 0.5*x*(1+erf(x/sqrt(2)))
    return 0.5f * v * (1.0f + erff(v * 0.70710678118654752440f));
}

__device__ __forceinline__ void red_add_v4(float* p, float a, float b, float c, float d) {
    asm volatile("red.global.add.v4.f32 [%0], {%1, %2, %3, %4};"
                 :: "l"(p), "f"(a), "f"(b), "f"(c), "f"(d) : "memory");
}

// ---------------- fold kernel: BN -> weights ----------------
__global__ void fold_kernel(
    const float* __restrict__ m_g1, const float* __restrict__ m_b1,
    const float* __restrict__ m_mu1, const float* __restrict__ m_v1,
    const float* __restrict__ m_W1, const float* __restrict__ m_c1,
    const float* __restrict__ m_g2, const float* __restrict__ m_b2,
    const float* __restrict__ m_mu2, const float* __restrict__ m_v2,
    const float* __restrict__ m_W2, const float* __restrict__ m_c2,
    const float* __restrict__ u_g1, const float* __restrict__ u_b1,
    const float* __restrict__ u_mu1, const float* __restrict__ u_v1,
    const float* __restrict__ u_W1, const float* __restrict__ u_c1,
    const float* __restrict__ u_g2, const float* __restrict__ u_b2,
    const float* __restrict__ u_mu2, const float* __restrict__ u_v2,
    const float* __restrict__ u_W2, const float* __restrict__ u_c2)
{
    int t = blockIdx.x * blockDim.x + threadIdx.x;
    if (t < 4096) {
        int k = t >> 6;
        float s = m_g1[k] * rsqrtf(m_v1[k] + BN_EPS);
        g_Wm1[t] = s * m_W1[t];
    } else if (t < 8192) {
        int i = t - 4096; int k = i >> 6;
        float s = m_g2[k] * rsqrtf(m_v2[k] + BN_EPS);
        g_Wm2[i] = s * m_W2[i];
    } else if (t < 16384) {
        int i = t - 8192; int k = i >> 6;
        float s = u_g1[k] * rsqrtf(u_v1[k] + BN_EPS);
        g_Wu1[i] = s * u_W1[i];
    } else if (t < 20480) {
        int i = t - 16384; int k = i >> 6;
        float s = u_g2[k] * rsqrtf(u_v2[k] + BN_EPS);
        g_Wu2[i] = s * u_W2[i];
    } else if (t < 20544) {
        int j = t - 20480;
        float sum = m_c1[j];
        for (int k = 0; k < DF; k++) {
            float s = m_g1[k] * rsqrtf(m_v1[k] + BN_EPS);
            float tt = m_b1[k] - m_mu1[k] * s;
            sum += tt * m_W1[k * HF + j];
        }
        g_cm1[j] = sum;
    } else if (t < 20608) {
        int j = t - 20544;
        float sum = m_c2[j];
        for (int k = 0; k < HF; k++) {
            float s = m_g2[k] * rsqrtf(m_v2[k] + BN_EPS);
            float tt = m_b2[k] - m_mu2[k] * s;
            sum += tt * m_W2[k * HF + j];
        }
        g_cm2[j] = sum;
    } else if (t < 20672) {
        int j = t - 20608;
        float sum = u_c1[j];
        for (int k = 0; k < DF + HF; k++) {
            float s = u_g1[k] * rsqrtf(u_v1[k] + BN_EPS);
            float tt = u_b1[k] - u_mu1[k] * s;
            sum += tt * u_W1[k * HF + j];
        }
        g_cu1[j] = sum;
    } else if (t < 20736) {
        int j = t - 20672;
        float sum = u_c2[j];
        for (int k = 0; k < HF; k++) {
            float s = u_g2[k] * rsqrtf(u_v2[k] + BN_EPS);
            float tt = u_b2[k] - u_mu2[k] * s;
            sum += tt * u_W2[k * HF + j];
        }
        g_cu2[j] = sum;
    }
}

// ---------------- zero accumulators ----------------
__global__ void zero_kernel() {
    size_t total = (size_t)NODES * HF;
    for (size_t i = blockIdx.x * (size_t)blockDim.x + threadIdx.x;
         i < total; i += (size_t)gridDim.x * blockDim.x) {
        g_agg[i] = 0.0f;
        if (i < NODES) g_cnt[i] = 0.0f;
    }
}

// ---------------- MLP layer building blocks ----------------
// 64->64 layer, weights in smem (broadcast LDS.128), gelu, write to per-thread smem column
__device__ __forceinline__ void layer64_smem(const float* __restrict__ W,
                                             const float* __restrict__ b,
                                             const float x[64], float* col) {
#pragma unroll 1
    for (int q = 0; q < 16; q++) {
        float4 bb = *(const float4*)(b + q * 4);
        float a0 = bb.x, a1 = bb.y, a2 = bb.z, a3 = bb.w;
        const float* wp = W + q * 4;
#pragma unroll
        for (int k = 0; k < 64; k++) {
            float4 w = *(const float4*)(wp + k * 64);
            a0 = fmaf(x[k], w.x, a0);
            a1 = fmaf(x[k], w.y, a1);
            a2 = fmaf(x[k], w.z, a2);
            a3 = fmaf(x[k], w.w, a3);
        }
        col[(q * 4 + 0) * 128] = gelu_f(a0);
        col[(q * 4 + 1) * 128] = gelu_f(a1);
        col[(q * 4 + 2) * 128] = gelu_f(a2);
        col[(q * 4 + 3) * 128] = gelu_f(a3);
    }
}

// 64->64 layer, weights in global (uniform __ldg, L1-resident broadcast)
__device__ __forceinline__ void layer64_glob(const float* __restrict__ W,
                                             const float* __restrict__ b,
                                             const float x[64], float* col) {
#pragma unroll 1
    for (int q = 0; q < 16; q++) {
        float4 bb = *(const float4*)(b + q * 4);
        float a0 = bb.x, a1 = bb.y, a2 = bb.z, a3 = bb.w;
        const float4* wp = (const float4*)(W + q * 4);
#pragma unroll
        for (int k = 0; k < 64; k++) {
            float4 w = __ldg((const float4*)((const float*)wp + k * 64));
            a0 = fmaf(x[k], w.x, a0);
            a1 = fmaf(x[k], w.y, a1);
            a2 = fmaf(x[k], w.z, a2);
            a3 = fmaf(x[k], w.w, a3);
        }
        col[(q * 4 + 0) * 128] = gelu_f(a0);
        col[(q * 4 + 1) * 128] = gelu_f(a1);
        col[(q * 4 + 2) * 128] = gelu_f(a2);
        col[(q * 4 + 3) * 128] = gelu_f(a3);
    }
}

// final edge layer: er = gelu(x@We2+c), msg read from smem column, red-add gated msg
__device__ __forceinline__ void layer64_final(const float* __restrict__ W,
                                              const float* __restrict__ b,
                                              const float x[64],
                                              const float* msgcol, float* aggrow) {
#pragma unroll 1
    for (int q = 0; q < 16; q++) {
        float4 bb = *(const float4*)(b + q * 4);
        float a0 = bb.x, a1 = bb.y, a2 = bb.z, a3 = bb.w;
        const float* wp = W + q * 4;
#pragma unroll
        for (int k = 0; k < 64; k++) {
            float4 w = __ldg((const float4*)(wp + k * 64));
            a0 = fmaf(x[k], w.x, a0);
            a1 = fmaf(x[k], w.y, a1);
            a2 = fmaf(x[k], w.z, a2);
            a3 = fmaf(x[k], w.w, a3);
        }
        float e0 = gelu_f(a0), e1 = gelu_f(a1), e2 = gelu_f(a2), e3 = gelu_f(a3);
        float m0 = msgcol[(q * 4 + 0) * 128];
        float m1 = msgcol[(q * 4 + 1) * 128];
        float m2 = msgcol[(q * 4 + 2) * 128];
        float m3 = msgcol[(q * 4 + 3) * 128];
        red_add_v4(aggrow + q * 4, m0 * e0, m1 * e1, m2 * e2, m3 * e3);
    }
}

// ---------------- edge kernel: fused message + gate + scatter ----------------
// smem layout (floats): Wm1 4096 | Wm2 4096 | biases 256 | io 8192 | io2 8192 = 24832 (~97KB)
__global__ void __launch_bounds__(128, 2)
edge_kernel(const float* __restrict__ nf, const float* __restrict__ ef,
            const int* __restrict__ src, const int* __restrict__ dst,
            const float* __restrict__ We1, const float* __restrict__ ce1,
            const float* __restrict__ We2, const float* __restrict__ ce2,
            int E)
{
    extern __shared__ float sm[];
    float* sWm1 = sm;
    float* sWm2 = sm + 4096;
    float* sb   = sm + 8192;   // [0:64) cm1, [64:128) cm2, [128:192) ce1, [192:256) ce2
    float* io   = sm + 8448;
    float* io2  = sm + 8448 + 8192;

    for (int i = threadIdx.x; i < 4096; i += 128) {
        sWm1[i] = g_Wm1[i];
        sWm2[i] = g_Wm2[i];
    }
    if (threadIdx.x < 64) {
        int i = threadIdx.x;
        sb[i]       = g_cm1[i];
        sb[64 + i]  = g_cm2[i];
        sb[128 + i] = ce1[i];
        sb[192 + i] = ce2[i];
    }
    __syncthreads();

    float* col  = io  + threadIdx.x;
    float* col2 = io2 + threadIdx.x;

    for (int e = blockIdx.x * 128 + threadIdx.x; e < E; e += gridDim.x * 128) {
        int d = dst[e];
        int s = src[e];
        float x[64];

        // gather neighbour features (L2-resident)
        const float4* nrow = (const float4*)(nf + (size_t)d * 64);
#pragma unroll
        for (int k = 0; k < 16; k++) {
            float4 v = __ldg(nrow + k);
            x[4 * k + 0] = v.x; x[4 * k + 1] = v.y;
            x[4 * k + 2] = v.z; x[4 * k + 3] = v.w;
        }
        // message MLP (BN folded)
        layer64_smem(sWm1, sb, x, col);
#pragma unroll
        for (int k = 0; k < 64; k++) x[k] = col[k * 128];
        layer64_smem(sWm2, sb + 64, x, col);   // io now holds msg

        // edge transformer
        const float4* erow = (const float4*)(ef + (size_t)e * 64);
#pragma unroll
        for (int k = 0; k < 16; k++) {
            float4 v = __ldg(erow + k);
            x[4 * k + 0] = v.x; x[4 * k + 1] = v.y;
            x[4 * k + 2] = v.z; x[4 * k + 3] = v.w;
        }
        layer64_glob(We1, sb + 128, x, col2);
#pragma unroll
        for (int k = 0; k < 64; k++) x[k] = col2[k * 128];
        // final gate + scatter-add
        layer64_final(We2, sb + 192, x, col, g_agg + (size_t)s * 64);
        atomicAdd(&g_cnt[s], 1.0f);
    }
}

// ---------------- node kernel: mean + update MLP ----------------
// smem (floats): Wu1 8192 | Wu2 4096 | biases 128 | io 8192 = 20608 (~80.5KB)
__global__ void __launch_bounds__(128, 2)
node_kernel(const float* __restrict__ nf, float* __restrict__ out, int N)
{
    extern __shared__ float sm[];
    float* sW1 = sm;
    float* sW2 = sm + 8192;
    float* sb  = sm + 12288;  // [0:64) cu1, [64:128) cu2
    float* io  = sm + 12416;

    for (int i = threadIdx.x; i < 8192; i += 128) sW1[i] = g_Wu1[i];
    for (int i = threadIdx.x; i < 4096; i += 128) sW2[i] = g_Wu2[i];
    if (threadIdx.x < 64) {
        sb[threadIdx.x]      = g_cu1[threadIdx.x];
        sb[64 + threadIdx.x] = g_cu2[threadIdx.x];
    }
    __syncthreads();

    int n = blockIdx.x * 128 + threadIdx.x;
    if (n >= N) return;

    float x[128];
    const float4* nrow = (const float4*)(nf + (size_t)n * 64);
#pragma unroll
    for (int k = 0; k < 16; k++) {
        float4 v = __ldg(nrow + k);
        x[4 * k + 0] = v.x; x[4 * k + 1] = v.y;
        x[4 * k + 2] = v.z; x[4 * k + 3] = v.w;
    }
    float c = g_cnt[n];
    float inv = 1.0f / fmaxf(c, 1.0f);
    const float4* arow = (const float4*)(g_agg + (size_t)n * 64);
#pragma unroll
    for (int k = 0; k < 16; k++) {
        float4 v = arow[k];
        x[64 + 4 * k + 0] = v.x * inv; x[64 + 4 * k + 1] = v.y * inv;
        x[64 + 4 * k + 2] = v.z * inv; x[64 + 4 * k + 3] = v.w * inv;
    }

    float* col = io + threadIdx.x;
    // layer 1: 128 -> 64
#pragma unroll 1
    for (int q = 0; q < 16; q++) {
        float4 bb = *(const float4*)(sb + q * 4);
        float a0 = bb.x, a1 = bb.y, a2 = bb.z, a3 = bb.w;
        const float* wp = sW1 + q * 4;
#pragma unroll
        for (int k = 0; k < 128; k++) {
            float4 w = *(const float4*)(wp + k * 64);
            a0 = fmaf(x[k], w.x, a0);
            a1 = fmaf(x[k], w.y, a1);
            a2 = fmaf(x[k], w.z, a2);
            a3 = fmaf(x[k], w.w, a3);
        }
        col[(q * 4 + 0) * 128] = gelu_f(a0);
        col[(q * 4 + 1) * 128] = gelu_f(a1);
        col[(q * 4 + 2) * 128] = gelu_f(a2);
        col[(q * 4 + 3) * 128] = gelu_f(a3);
    }
#pragma unroll
    for (int k = 0; k < 64; k++) x[k] = col[k * 128];
    // layer 2: 64 -> 64, write output directly
    float4* orow = (float4*)(out + (size_t)n * 64);
#pragma unroll 1
    for (int q = 0; q < 16; q++) {
        float4 bb = *(const float4*)(sb + 64 + q * 4);
        float a0 = bb.x, a1 = bb.y, a2 = bb.z, a3 = bb.w;
        const float* wp = sW2 + q * 4;
#pragma unroll
        for (int k = 0; k < 64; k++) {
            float4 w = *(const float4*)(wp + k * 64);
            a0 = fmaf(x[k], w.x, a0);
            a1 = fmaf(x[k], w.y, a1);
            a2 = fmaf(x[k], w.z, a2);
            a3 = fmaf(x[k], w.w, a3);
        }
        float4 o;
        o.x = gelu_f(a0); o.y = gelu_f(a1); o.z = gelu_f(a2); o.w = gelu_f(a3);
        orow[q] = o;
    }
}

// ---------------- launch ----------------
extern "C" void kernel_launch(void* const* d_in, const int* in_sizes, int n_in,
                              void* d_out, int out_size)
{
    // Resolve input ordering: setup-dict order has src (800000) at idx 2;
    // reference-signature order has m_g1 (64) at idx 2.
    bool dictOrder = (in_sizes[2] > 64);
    const float* nf = (const float*)d_in[0];
    const float* ef = (const float*)d_in[1];
    const int* src = (const int*)d_in[dictOrder ? 2 : 30];
    const int* dst = (const int*)d_in[dictOrder ? 3 : 31];
    int p0 = dictOrder ? 4 : 2;
    const float* P[28];
    for (int i = 0; i < 28; i++) P[i] = (const float*)d_in[p0 + i];
    // P: 0 m_g1,1 m_b1,2 m_mu1,3 m_v1,4 m_W1,5 m_c1,6 m_g2,7 m_b2,8 m_mu2,9 m_v2,
    //    10 m_W2,11 m_c2,12 e_W1,13 e_c1,14 e_W2,15 e_c2,16 u_g1,17 u_b1,18 u_mu1,
    //    19 u_v1,20 u_W1,21 u_c1,22 u_g2,23 u_b2,24 u_mu2,25 u_v2,26 u_W2,27 u_c2

    int E = in_sizes[1] / 64;
    int N = in_sizes[0] / 64;

    cudaFuncSetAttribute(edge_kernel, cudaFuncAttributeMaxDynamicSharedMemorySize,
                         24832 * (int)sizeof(float));
    cudaFuncSetAttribute(node_kernel, cudaFuncAttributeMaxDynamicSharedMemorySize,
                         20608 * (int)sizeof(float));

    fold_kernel<<<(20736 + 255) / 256, 256>>>(
        P[0], P[1], P[2], P[3], P[4], P[5], P[6], P[7], P[8], P[9], P[10], P[11],
        P[16], P[17], P[18], P[19], P[20], P[21], P[22], P[23], P[24], P[25], P[26], P[27]);
    zero_kernel<<<2048, 256>>>();
    edge_kernel<<<296, 128, 24832 * sizeof(float)>>>(
        nf, ef, src, dst, P[12], P[13], P[14], P[15], E);
    node_kernel<<<(N + 127) / 128, 128, 20608 * sizeof(float)>>>(
        nf, (float*)d_out, N);
}